// round 3
// baseline (speedup 1.0000x reference)
#include <cuda_runtime.h>
#include <cuda_bf16.h>

// Scratch (allocation-free rule: __device__ globals).
#define MAX_S 262144
__device__ float    g_tw[MAX_S];
__device__ unsigned g_last[MAX_S];   // bit pattern of segment-max timestamp (all t > 0)

#define BETA 0.8f

// ---------------------------------------------------------------------------
// Zero the per-segment scratch.
__global__ void twma_init_kernel(int S) {
    int i = blockIdx.x * blockDim.x + threadIdx.x;
    if (i < S) {
        g_tw[i]   = 0.0f;
        g_last[i] = 0u;
    }
}

// ---------------------------------------------------------------------------
// Segment max of timestamps. Timestamps are positive, so the uint bit pattern
// order matches float order; init 0 means empty segments end with last_t = 0,
// which is exactly the reference's where(tw>0, last_t, 0) output.
__global__ void twma_max_kernel(const float* __restrict__ ts,
                                const int*   __restrict__ ids,
                                int N) {
    int i = blockIdx.x * blockDim.x + threadIdx.x;
    if (i < N) {
        atomicMax(&g_last[ids[i]], __float_as_uint(ts[i]));
    }
}

// ---------------------------------------------------------------------------
// Main pass: one thread per (row, 4-col chunk).
// Reads messages coalesced as float4, computes w per row (t/seg loads are
// warp-broadcast L2 hits), scatters with vectorized no-return reduction
// (red.global.add.v4.f32) into the agg region of d_out, and accumulates the
// per-segment weight total once per row.
__global__ void twma_acc_kernel(const float4* __restrict__ msg,
                                const float*  __restrict__ ts,
                                const int*    __restrict__ ids,
                                float* __restrict__ out,
                                int N, int C /* = D/4 */) {
    long long idx = (long long)blockIdx.x * blockDim.x + threadIdx.x;
    long long total = (long long)N * C;
    if (idx >= total) return;
    int i = (int)(idx / C);
    int c = (int)(idx - (long long)i * C);

    int   seg = ids[i];
    float t   = ts[i];
    float lt  = __uint_as_float(g_last[seg]);
    float w   = __expf(BETA * (t - lt));     // w in (0, 1], no overflow

    float4 m = msg[(long long)i * C + c];
    float4* dst = reinterpret_cast<float4*>(out) + ((long long)seg * C + c);

#if __CUDA_ARCH__ >= 900
    asm volatile("red.global.add.v4.f32 [%0], {%1, %2, %3, %4};"
                 :: "l"(dst), "f"(m.x * w), "f"(m.y * w),
                    "f"(m.z * w), "f"(m.w * w)
                 : "memory");
#else
    float* d = reinterpret_cast<float*>(dst);
    atomicAdd(d + 0, m.x * w);
    atomicAdd(d + 1, m.y * w);
    atomicAdd(d + 2, m.z * w);
    atomicAdd(d + 3, m.w * w);
#endif

    if (c == 0) {
        atomicAdd(&g_tw[seg], w);
    }
}

// ---------------------------------------------------------------------------
// Finalize: divide agg rows by total weight in place; write last_t tail.
// Empty segments: agg row is already zero (memset) and inv = 0; last bits = 0.
__global__ void twma_fin_kernel(float* __restrict__ out, int S, int C, int D) {
    int idx = blockIdx.x * blockDim.x + threadIdx.x;   // S*C threads
    if (idx >= S * C) return;
    int s = idx / C;
    int c = idx - s * C;

    float tw  = g_tw[s];
    float inv = (tw > 0.0f) ? (1.0f / tw) : 0.0f;

    float4* p = reinterpret_cast<float4*>(out) + idx;
    float4 v = *p;
    v.x *= inv; v.y *= inv; v.z *= inv; v.w *= inv;
    *p = v;

    if (c == 0) {
        out[(long long)S * D + s] = __uint_as_float(g_last[s]);
    }
}

// ---------------------------------------------------------------------------
extern "C" void kernel_launch(void* const* d_in, const int* in_sizes, int n_in,
                              void* d_out, int out_size) {
    const float* msg = (const float*)d_in[0];   // [N, D] fp32
    const float* ts  = (const float*)d_in[1];   // [N]    fp32
    const int*   ids = (const int*)d_in[2];     // [N]    int32

    int N = in_sizes[1];
    int D = in_sizes[0] / N;          // 256
    int S = out_size / (D + 1);       // 65536 (out = S*D agg + S last_t)
    int C = D / 4;

    float* out = (float*)d_out;

    // Zero the agg accumulation region (last_t tail is fully overwritten).
    cudaMemsetAsync(d_out, 0, (size_t)S * D * sizeof(float));

    twma_init_kernel<<<(S + 255) / 256, 256>>>(S);
    twma_max_kernel<<<(N + 255) / 256, 256>>>(ts, ids, N);

    long long total = (long long)N * C;
    unsigned blocks = (unsigned)((total + 255) / 256);
    twma_acc_kernel<<<blocks, 256>>>((const float4*)msg, ts, ids, out, N, C);

    twma_fin_kernel<<<(S * C + 255) / 256, 256>>>(out, S, C, D);
}

// round 4
// speedup vs baseline: 1.6510x; 1.6510x over previous
#include <cuda_runtime.h>
#include <cuda_bf16.h>

// Scratch (allocation-free rule: __device__ globals).
#define MAX_S 262144
#define MAX_N 2097152
__device__ int      g_count[MAX_S];
__device__ int      g_base[MAX_S];
__device__ int      g_cursor[MAX_S];
__device__ int      g_bsum[1024];
__device__ unsigned g_last[MAX_S];    // bit pattern of segment-max timestamp (all t > 0)
__device__ int      g_perm[MAX_N];    // row indices grouped by segment

#define BETA 0.8f
#define SCAN_B 1024

// ---------------------------------------------------------------------------
__global__ void twma_init_kernel(int S) {
    int i = blockIdx.x * blockDim.x + threadIdx.x;
    if (i < S) {
        g_count[i] = 0;
        g_last[i]  = 0u;
    }
}

// Histogram of segment ids + segment-max of timestamps (uint order == float
// order since all t > 0; init 0 => empty segments output last_t = 0, matching
// the reference's where(tw>0, last_t, 0)).
__global__ void twma_hist_kernel(const int* __restrict__ ids,
                                 const float* __restrict__ ts,
                                 int N) {
    int i = blockIdx.x * blockDim.x + threadIdx.x;
    if (i < N) {
        int s = ids[i];
        atomicAdd(&g_count[s], 1);
        atomicMax(&g_last[s], __float_as_uint(ts[i]));
    }
}

// ---------------------------------------------------------------------------
// Exclusive scan of g_count -> g_base (3 kernels: per-block scan, scan of
// block sums, offset add + cursor init).
__global__ void twma_scan1_kernel(int S) {
    __shared__ int sh[SCAN_B];
    int tid = threadIdx.x;
    int gid = blockIdx.x * SCAN_B + tid;
    int v = (gid < S) ? g_count[gid] : 0;
    sh[tid] = v;
    __syncthreads();
    for (int off = 1; off < SCAN_B; off <<= 1) {
        int t = (tid >= off) ? sh[tid - off] : 0;
        __syncthreads();
        sh[tid] += t;
        __syncthreads();
    }
    int incl = sh[tid];
    if (gid < S) g_base[gid] = incl - v;          // exclusive
    if (tid == SCAN_B - 1) g_bsum[blockIdx.x] = incl;
}

__global__ void twma_scan2_kernel(int nb) {
    __shared__ int sh[SCAN_B];
    int tid = threadIdx.x;
    int v = (tid < nb) ? g_bsum[tid] : 0;
    sh[tid] = v;
    __syncthreads();
    for (int off = 1; off < SCAN_B; off <<= 1) {
        int t = (tid >= off) ? sh[tid - off] : 0;
        __syncthreads();
        sh[tid] += t;
        __syncthreads();
    }
    if (tid < nb) g_bsum[tid] = sh[tid] - v;      // exclusive
}

__global__ void twma_scan3_kernel(int S) {
    int gid = blockIdx.x * SCAN_B + threadIdx.x;
    if (gid < S) {
        int b = g_base[gid] + g_bsum[blockIdx.x];
        g_base[gid]   = b;
        g_cursor[gid] = b;
    }
}

// ---------------------------------------------------------------------------
// Bucket rows by segment.
__global__ void twma_scatter_kernel(const int* __restrict__ ids, int N) {
    int i = blockIdx.x * blockDim.x + threadIdx.x;
    if (i < N) {
        int p = atomicAdd(&g_cursor[ids[i]], 1);
        g_perm[p] = i;
    }
}

// ---------------------------------------------------------------------------
// One warp per (segment, 128-float column tile). Gather the segment's rows,
// accumulate w*m in registers, write agg/tw and last_t exactly once.
// Each warp's message load: 32 lanes x float4 = 512B contiguous (coalesced).
__global__ void twma_seg_kernel(const float4* __restrict__ msg,
                                const float*  __restrict__ ts,
                                float* __restrict__ out,
                                int S, int C /* D/4 */, int D) {
    int gw   = (blockIdx.x * blockDim.x + threadIdx.x) >> 5;
    int lane = threadIdx.x & 31;
    int tilesPerSeg = C >> 5;                 // D/128 column tiles
    int seg  = gw / tilesPerSeg;
    int tile = gw - seg * tilesPerSeg;
    if (seg >= S) return;

    int   base = g_base[seg];
    int   cnt  = g_count[seg];
    unsigned lb = g_last[seg];
    float lt   = __uint_as_float(lb);
    int   col  = (tile << 5) + lane;          // float4 index within row

    float4 acc = make_float4(0.f, 0.f, 0.f, 0.f);
    float  tw  = 0.f;

    #pragma unroll 4
    for (int r = 0; r < cnt; r++) {
        int   i = g_perm[base + r];
        float w = __expf(BETA * (ts[i] - lt));   // broadcast loads, w in (0,1]
        tw += w;
        float4 m = msg[(long long)i * C + col];
        acc.x += w * m.x;
        acc.y += w * m.y;
        acc.z += w * m.z;
        acc.w += w * m.w;
    }

    float inv = (cnt > 0) ? (1.0f / tw) : 0.0f;
    reinterpret_cast<float4*>(out)[(long long)seg * C + col] =
        make_float4(acc.x * inv, acc.y * inv, acc.z * inv, acc.w * inv);

    if (tile == 0 && lane == 0) {
        out[(long long)S * D + seg] = __uint_as_float(lb);  // 0 for empty segs
    }
}

// ---------------------------------------------------------------------------
extern "C" void kernel_launch(void* const* d_in, const int* in_sizes, int n_in,
                              void* d_out, int out_size) {
    const float* msg = (const float*)d_in[0];   // [N, D] fp32
    const float* ts  = (const float*)d_in[1];   // [N]    fp32
    const int*   ids = (const int*)d_in[2];     // [N]    int32

    int N = in_sizes[1];
    int D = in_sizes[0] / N;          // 256
    int S = out_size / (D + 1);       // 65536 (out = S*D agg + S last_t)
    int C = D / 4;

    float* out = (float*)d_out;

    twma_init_kernel<<<(S + 255) / 256, 256>>>(S);
    twma_hist_kernel<<<(N + 255) / 256, 256>>>(ids, ts, N);

    int nb = (S + SCAN_B - 1) / SCAN_B;         // 64 for S=65536 (<=1024)
    twma_scan1_kernel<<<nb, SCAN_B>>>(S);
    twma_scan2_kernel<<<1, SCAN_B>>>(nb);
    twma_scan3_kernel<<<nb, SCAN_B>>>(S);

    twma_scatter_kernel<<<(N + 255) / 256, 256>>>(ids, N);

    long long warps  = (long long)S * (C >> 5); // one warp per (seg, 128-col tile)
    long long threads = warps * 32;
    unsigned blocks  = (unsigned)((threads + 255) / 256);
    twma_seg_kernel<<<blocks, 256>>>((const float4*)msg, ts, out, S, C, D);
}